// round 13
// baseline (speedup 1.0000x reference)
#include <cuda_runtime.h>
#include <math.h>

#define BATCH   16384
#define N_CAT   26
#define N_CONT  13
#define EDIM    128
#define VOCAB   100000
#define N_ROWS  27            // N_CAT + 1
#define N_PAIRS 351           // 27*26/2
#define TOP_IN  479           // 351 + 128
#define X0_LD   480           // padded stride

// ------------------------- scratch (device globals) -------------------------
__device__ float g_h1[BATCH * 512];     // bottom L1 out; reused as t3 (B x 512)
__device__ float g_h2[BATCH * 256];     // bottom L2 out; reused as t4 (B x 256)
__device__ float g_dense[BATCH * 128];  // bottom MLP output
__device__ float g_x0[BATCH * X0_LD];   // top MLP input (351 inter + 128 dense + 1 pad)
__device__ float g_t1[BATCH * 1024];
__device__ float g_t2[BATCH * 1024];
__device__ float g_Wt1p[X0_LD * 1024];  // Wt1 padded K 479 -> 480 (row 479 = 0)
__device__ int   g_is64;

// ------------------------- f32x2 packed math helpers ------------------------
__device__ __forceinline__ unsigned long long pack2(float x, float y) {
    unsigned long long d;
    asm("mov.b64 %0, {%1, %2};" : "=l"(d) : "f"(x), "f"(y));
    return d;
}
__device__ __forceinline__ unsigned long long ffma2(unsigned long long a,
                                                    unsigned long long b,
                                                    unsigned long long c) {
    unsigned long long d;
    asm("fma.rn.f32x2 %0, %1, %2, %3;" : "=l"(d) : "l"(a), "l"(b), "l"(c));
    return d;
}

// ------------------------- idx dtype detector -------------------------------
// If cat_idx is int64 (values < 100000), every odd 32-bit word of the buffer
// is 0. If it is int32, odd words are random indices in [0, 100000) -> the
// probability all 2048 are zero is ~0.
__global__ void detect_idx_kernel(const unsigned int* __restrict__ w) {
    __shared__ int ok;
    if (threadIdx.x == 0) ok = 1;
    __syncthreads();
    bool bad = false;
    for (int i = threadIdx.x; i < 2048; i += 256)
        if (w[2 * i + 1] != 0u) bad = true;
    if (bad) ok = 0;
    __syncthreads();
    if (threadIdx.x == 0) g_is64 = ok;
}

// ------------------------- bottom MLP layer 1 (K=13) ------------------------
// 4 rows per block, 128 threads; W row chunks reused across the 4 rows.
__global__ void dense1_kernel(const float* __restrict__ X,
                              const float* __restrict__ W,
                              const float* __restrict__ bias) {
    __shared__ float xs[4][N_CONT];
    const int row0 = blockIdx.x * 4;
    const int t = threadIdx.x;
    if (t < 4 * N_CONT) xs[t / N_CONT][t % N_CONT] = X[(size_t)(row0 + t / N_CONT) * N_CONT + (t % N_CONT)];
    __syncthreads();

    const int n0 = t * 4;
    float4 acc[4];
    #pragma unroll
    for (int r = 0; r < 4; r++) acc[r] = make_float4(0.f, 0.f, 0.f, 0.f);

    #pragma unroll
    for (int k = 0; k < N_CONT; k++) {
        float4 w = *(const float4*)&W[k * 512 + n0];
        #pragma unroll
        for (int r = 0; r < 4; r++) {
            float xk = xs[r][k];
            acc[r].x += xk * w.x; acc[r].y += xk * w.y;
            acc[r].z += xk * w.z; acc[r].w += xk * w.w;
        }
    }
    float4 bb = *(const float4*)&bias[n0];
    #pragma unroll
    for (int r = 0; r < 4; r++) {
        float4 v;
        v.x = fmaxf(acc[r].x + bb.x, 0.f);
        v.y = fmaxf(acc[r].y + bb.y, 0.f);
        v.z = fmaxf(acc[r].z + bb.z, 0.f);
        v.w = fmaxf(acc[r].w + bb.w, 0.f);
        *(float4*)&g_h1[(size_t)(row0 + r) * 512 + n0] = v;
    }
}

// ------------------------- Wt1 pad kernel ------------------------------------
__global__ void pad_wt1_kernel(const float* __restrict__ W) {
    int i = blockIdx.x * 256 + threadIdx.x;
    if (i < X0_LD * 1024)
        g_Wt1p[i] = (i < TOP_IN * 1024) ? W[i] : 0.f;
}

// ------------------------- fused gather + interactions ----------------------
// One block per batch row. Gathers 26 embedding rows + dense row into smem,
// then computes the 351 upper-triangle dot products straight into g_x0.
__global__ void interact_kernel(const void* __restrict__ cat,
                                const float* __restrict__ emb) {
    __shared__ float Zs[N_ROWS * EDIM];   // 13824 B
    const int b = blockIdx.x;
    const int t = threadIdx.x;            // 384 threads = 12 warps
    const int lane = t & 31;
    const int warp = t >> 5;
    const int is64 = g_is64;

    for (int row = warp; row < N_ROWS; row += 12) {
        const float4* src;
        if (row < N_CAT) {
            long long idx;
            size_t e = (size_t)b * N_CAT + row;
            if (is64) idx = ((const long long*)cat)[e];
            else      idx = (long long)((const int*)cat)[e];
            src = (const float4*)(emb + ((long long)row * VOCAB + idx) * EDIM);
        } else {
            src = (const float4*)(g_dense + (size_t)b * EDIM);
        }
        ((float4*)(Zs + row * EDIM))[lane] = src[lane];
    }
    __syncthreads();

    if (t < N_PAIRS) {
        // decode pair index -> (i, j), row-major upper triangle k=1
        int i = 0, rem = t, rl = N_CAT;
        while (rem >= rl) { rem -= rl; rl--; i++; }
        int j = i + 1 + rem;
        const float4* zi = (const float4*)(Zs + i * EDIM);
        const float4* zj = (const float4*)(Zs + j * EDIM);
        float acc = 0.f;
        #pragma unroll
        for (int e = 0; e < EDIM / 4; e++) {
            float4 a = zi[e], c = zj[e];
            acc += a.x * c.x + a.y * c.y + a.z * c.z + a.w * c.w;
        }
        g_x0[(size_t)b * X0_LD + t] = acc;
    } else if (t == N_PAIRS) {
        g_x0[(size_t)b * X0_LD + (X0_LD - 1)] = 0.f;  // pad column
    }
}

// ------------------------- SGEMM (f32x2 packed) ------------------------------
// C[M,N] = relu?(A[M,K] @ W[K,N] + bias). 128x128x16 tile, 256 thr, 8x8/thread
// via 8x4 packed f32x2 accumulators. Requires K%16==0, N%128==0, M%128==0.
__global__ __launch_bounds__(256, 2)
void sgemm_bias_act(const float* __restrict__ A, int lda,
                    const float* __restrict__ Wg,
                    const float* __restrict__ bias,
                    float* __restrict__ C, int ldc,
                    float* __restrict__ C2, int ldc2,
                    int N, int K, int relu) {
    __shared__ unsigned long long As2[16][128];  // A values pre-packed (a,a)
    __shared__ unsigned long long Bs2[16][64];   // B pairs (n, n+1)

    const int tid = threadIdx.x;
    const int tx = tid & 15;
    const int ty = tid >> 4;
    const int rm = blockIdx.y * 128;
    const int bn = blockIdx.x * 128;

    unsigned long long acc[8][4];
    #pragma unroll
    for (int i = 0; i < 8; i++)
        #pragma unroll
        for (int jj = 0; jj < 4; jj++) acc[i][jj] = 0ull;

    const int ar = tid >> 2;
    const int akq = (tid & 3) << 2;
    const int bkr = tid >> 5;
    const int bn4 = (tid & 31) << 2;

    for (int k0 = 0; k0 < K; k0 += 16) {
        #pragma unroll
        for (int l = 0; l < 2; l++) {
            int rr = ar + l * 64;
            float4 a = *(const float4*)(A + (size_t)(rm + rr) * lda + k0 + akq);
            As2[akq + 0][rr] = pack2(a.x, a.x);
            As2[akq + 1][rr] = pack2(a.y, a.y);
            As2[akq + 2][rr] = pack2(a.z, a.z);
            As2[akq + 3][rr] = pack2(a.w, a.w);
        }
        #pragma unroll
        for (int l = 0; l < 2; l++) {
            int kk = bkr + l * 8;
            float4 bv = *(const float4*)(Wg + (size_t)(k0 + kk) * N + bn + bn4);
            *(float4*)((float*)&Bs2[kk][0] + bn4) = bv;
        }
        __syncthreads();

        #pragma unroll
        for (int k = 0; k < 16; k++) {
            ulonglong2 a0 = *(const ulonglong2*)&As2[k][ty * 8 + 0];
            ulonglong2 a1 = *(const ulonglong2*)&As2[k][ty * 8 + 2];
            ulonglong2 a2 = *(const ulonglong2*)&As2[k][ty * 8 + 4];
            ulonglong2 a3 = *(const ulonglong2*)&As2[k][ty * 8 + 6];
            ulonglong2 b0 = *(const ulonglong2*)&Bs2[k][tx * 4 + 0];
            ulonglong2 b1 = *(const ulonglong2*)&Bs2[k][tx * 4 + 2];
            unsigned long long ra[8] = {a0.x, a0.y, a1.x, a1.y, a2.x, a2.y, a3.x, a3.y};
            unsigned long long rb[4] = {b0.x, b0.y, b1.x, b1.y};
            #pragma unroll
            for (int i = 0; i < 8; i++)
                #pragma unroll
                for (int jj = 0; jj < 4; jj++)
                    acc[i][jj] = ffma2(ra[i], rb[jj], acc[i][jj]);
        }
        __syncthreads();
    }

    #pragma unroll
    for (int i = 0; i < 8; i++) {
        int row = rm + ty * 8 + i;
        #pragma unroll
        for (int jj = 0; jj < 4; jj++) {
            int c0 = bn + tx * 8 + jj * 2;
            float lo = __uint_as_float((unsigned)(acc[i][jj] & 0xffffffffull));
            float hi = __uint_as_float((unsigned)(acc[i][jj] >> 32));
            float v0 = lo + bias[c0];
            float v1 = hi + bias[c0 + 1];
            if (relu) { v0 = fmaxf(v0, 0.f); v1 = fmaxf(v1, 0.f); }
            C[(size_t)row * ldc + c0]     = v0;
            C[(size_t)row * ldc + c0 + 1] = v1;
            if (C2) {
                C2[(size_t)row * ldc2 + c0]     = v0;
                C2[(size_t)row * ldc2 + c0 + 1] = v1;
            }
        }
    }
}

// ------------------------- final dot + sigmoid -------------------------------
__global__ void final_kernel(const float* __restrict__ Wo,
                             const float* __restrict__ bo,
                             float* __restrict__ out) {
    __shared__ float ws[256];
    const int t = threadIdx.x;
    ws[t] = Wo[t];
    __syncthreads();
    const int lane = t & 31;
    const int warp = t >> 5;
    const int row = blockIdx.x * 8 + warp;
    const float* a = g_h2 + (size_t)row * 256;   // t4 lives in g_h2
    float acc = 0.f;
    #pragma unroll
    for (int q = 0; q < 8; q++)
        acc += a[lane + 32 * q] * ws[lane + 32 * q];
    #pragma unroll
    for (int off = 16; off; off >>= 1)
        acc += __shfl_down_sync(0xffffffffu, acc, off);
    if (lane == 0) {
        float x = acc + bo[0];
        out[row] = 1.f / (1.f + expf(-x));
    }
}

// ------------------------- launch ------------------------------------------
extern "C" void kernel_launch(void* const* d_in, const int* in_sizes, int n_in,
                              void* d_out, int out_size) {
    const float* dense_x = (const float*)d_in[0];
    const void*  cat_idx = d_in[1];
    const float* emb     = (const float*)d_in[2];
    const float* Wd1 = (const float*)d_in[3];
    const float* bd1 = (const float*)d_in[4];
    const float* Wd2 = (const float*)d_in[5];
    const float* bd2 = (const float*)d_in[6];
    const float* Wdf = (const float*)d_in[7];
    const float* bdf = (const float*)d_in[8];
    const float* Wt1 = (const float*)d_in[9];
    const float* bt1 = (const float*)d_in[10];
    const float* Wt2 = (const float*)d_in[11];
    const float* bt2 = (const float*)d_in[12];
    const float* Wt3 = (const float*)d_in[13];
    const float* bt3 = (const float*)d_in[14];
    const float* Wt4 = (const float*)d_in[15];
    const float* bt4 = (const float*)d_in[16];
    const float* Wo  = (const float*)d_in[17];
    const float* bo  = (const float*)d_in[18];
    float* out = (float*)d_out;

    float *p_h1, *p_h2, *p_dense, *p_x0, *p_t1, *p_t2, *p_Wt1p;
    cudaGetSymbolAddress((void**)&p_h1, g_h1);
    cudaGetSymbolAddress((void**)&p_h2, g_h2);
    cudaGetSymbolAddress((void**)&p_dense, g_dense);
    cudaGetSymbolAddress((void**)&p_x0, g_x0);
    cudaGetSymbolAddress((void**)&p_t1, g_t1);
    cudaGetSymbolAddress((void**)&p_t2, g_t2);
    cudaGetSymbolAddress((void**)&p_Wt1p, g_Wt1p);

    // 0. detect cat_idx dtype (int32 vs int64)
    detect_idx_kernel<<<1, 256>>>((const unsigned int*)cat_idx);

    // 1. bottom MLP layer 1: dense_x (B x 13) -> g_h1 (B x 512)
    dense1_kernel<<<BATCH / 4, 128>>>(dense_x, Wd1, bd1);

    // 2. h1 @ Wd2 -> g_h2 (B x 256)
    sgemm_bias_act<<<dim3(256 / 128, BATCH / 128), 256>>>(
        p_h1, 512, Wd2, bd2, p_h2, 256, (float*)0, 0, 256, 512, 1);

    // 3. h2 @ Wdf -> g_dense (B x 128) AND g_x0[:, 351:479]
    sgemm_bias_act<<<dim3(128 / 128, BATCH / 128), 256>>>(
        p_h2, 256, Wdf, bdf, p_dense, 128, p_x0 + N_PAIRS, X0_LD, 128, 256, 1);

    // 4. pad Wt1 K: 479 -> 480
    pad_wt1_kernel<<<(X0_LD * 1024) / 256, 256>>>(Wt1);

    // 5. fused embedding gather + pairwise interactions -> g_x0[:, 0:351]
    interact_kernel<<<BATCH, 384>>>(cat_idx, emb);

    // 6. top MLP
    sgemm_bias_act<<<dim3(1024 / 128, BATCH / 128), 256>>>(
        p_x0, X0_LD, p_Wt1p, bt1, p_t1, 1024, (float*)0, 0, 1024, X0_LD, 1);
    sgemm_bias_act<<<dim3(1024 / 128, BATCH / 128), 256>>>(
        p_t1, 1024, Wt2, bt2, p_t2, 1024, (float*)0, 0, 1024, 1024, 1);
    sgemm_bias_act<<<dim3(512 / 128, BATCH / 128), 256>>>(
        p_t2, 1024, Wt3, bt3, p_h1, 512, (float*)0, 0, 512, 1024, 1);   // t3 in g_h1
    sgemm_bias_act<<<dim3(256 / 128, BATCH / 128), 256>>>(
        p_h1, 512, Wt4, bt4, p_h2, 256, (float*)0, 0, 256, 512, 1);     // t4 in g_h2

    // 7. t4 @ Wo + bo -> sigmoid -> out (B x 1)
    final_kernel<<<BATCH / 8, 256>>>(Wo, bo, out);
}

// round 15
// speedup vs baseline: 2.2284x; 2.2284x over previous
#include <cuda_runtime.h>
#include <math.h>
#include <stdint.h>

#define BATCH   16384
#define N_CAT   26
#define N_CONT  13
#define EDIM    128
#define VOCAB   100000
#define N_ROWS  27
#define N_PAIRS 351
#define X0_LD   480          // [0:128) dense | [128:479) interactions | [479] pad

// ------------------------- scratch (device globals) -------------------------
__device__ float g_h1[BATCH * 512];     // bottom L1 out; reused as t3
__device__ float g_h2[BATCH * 256];     // bottom L2 out; reused as t4
__device__ float g_dense[BATCH * 128];
__device__ float g_x0[BATCH * X0_LD];
__device__ float g_t1[BATCH * 1024];
__device__ float g_t2[BATCH * 1024];
__device__ int   g_is64;

// tiled/swizzled tf32 weights: tiles of [128 N-rows x 32 K-cols] = 4096 floats
__device__ float g_wd2t[2  * 16 * 4096];   // 512x256
__device__ float g_wdft[1  * 8  * 4096];   // 256x128
__device__ float g_wt1t[8  * 15 * 4096];   // 480x1024 (remapped/padded)
__device__ float g_wt2t[8  * 32 * 4096];   // 1024x1024
__device__ float g_wt3t[4  * 32 * 4096];   // 1024x512
__device__ float g_wt4t[2  * 16 * 4096];   // 512x256

// ------------------------- PTX helpers --------------------------------------
__device__ __forceinline__ uint32_t smem_u32(const void* p) {
    uint32_t a;
    asm("{ .reg .u64 t; cvta.to.shared.u64 t, %1; cvt.u32.u64 %0, t; }" : "=r"(a) : "l"(p));
    return a;
}
__device__ __forceinline__ uint32_t f2tf32(float v) {
    uint32_t t;
    asm("cvt.rna.tf32.f32 %0, %1;" : "=r"(t) : "f"(v));
    return t;
}
__device__ __forceinline__ void ldsm4(uint32_t addr, uint32_t* r) {
    asm volatile("ldmatrix.sync.aligned.m8n8.x4.shared.b16 {%0,%1,%2,%3}, [%4];"
                 : "=r"(r[0]), "=r"(r[1]), "=r"(r[2]), "=r"(r[3]) : "r"(addr));
}

// ------------------------- idx dtype detector -------------------------------
__global__ void detect_idx_kernel(const unsigned int* __restrict__ w) {
    __shared__ int ok;
    if (threadIdx.x == 0) ok = 1;
    __syncthreads();
    bool bad = false;
    for (int i = threadIdx.x; i < 2048; i += 256)
        if (w[2 * i + 1] != 0u) bad = true;
    if (bad) ok = 0;
    __syncthreads();
    if (threadIdx.x == 0) g_is64 = ok;
}

// ------------------------- bottom MLP layer 1 (K=13) ------------------------
__global__ void dense1_kernel(const float* __restrict__ X,
                              const float* __restrict__ W,
                              const float* __restrict__ bias) {
    __shared__ float xs[4][N_CONT];
    const int row0 = blockIdx.x * 4;
    const int t = threadIdx.x;
    if (t < 4 * N_CONT) xs[t / N_CONT][t % N_CONT] = X[(size_t)(row0 + t / N_CONT) * N_CONT + (t % N_CONT)];
    __syncthreads();
    const int n0 = t * 4;
    float4 acc[4];
    #pragma unroll
    for (int r = 0; r < 4; r++) acc[r] = make_float4(0.f, 0.f, 0.f, 0.f);
    #pragma unroll
    for (int k = 0; k < N_CONT; k++) {
        float4 w = *(const float4*)&W[k * 512 + n0];
        #pragma unroll
        for (int r = 0; r < 4; r++) {
            float xk = xs[r][k];
            acc[r].x += xk * w.x; acc[r].y += xk * w.y;
            acc[r].z += xk * w.z; acc[r].w += xk * w.w;
        }
    }
    float4 bb = *(const float4*)&bias[n0];
    #pragma unroll
    for (int r = 0; r < 4; r++) {
        float4 v;
        v.x = fmaxf(acc[r].x + bb.x, 0.f);
        v.y = fmaxf(acc[r].y + bb.y, 0.f);
        v.z = fmaxf(acc[r].z + bb.z, 0.f);
        v.w = fmaxf(acc[r].w + bb.w, 0.f);
        *(float4*)&g_h1[(size_t)(row0 + r) * 512 + n0] = v;
    }
}

// ------------------------- weight tiling / swizzle prep ---------------------
// dst tile (nb, kc) = B smem image: row n_in (0..127) = N index, col k_in
// (0..31) = K index, byte off = n_in*128 + k_in*4, SW128-swizzled, tf32.
// remap!=0: Wt1 row permutation (dense rows 351..478 -> 0..127,
//           interaction rows 0..350 -> 128..478, row 479 = zero pad)
__global__ void prep_w_kernel(const float* __restrict__ W, float* __restrict__ dst,
                              int K, int Kp, int N, int remap) {
    int i = blockIdx.x * 256 + threadIdx.x;
    if (i >= Kp * N) return;
    int kd = i / N, n = i % N;
    int ks;
    if (remap) ks = (kd < 128) ? (kd + 351) : (kd < 479 ? kd - 128 : -1);
    else       ks = (kd < K) ? kd : -1;
    float v = (ks >= 0) ? W[(size_t)ks * N + n] : 0.f;
    uint32_t t = f2tf32(v);
    int kc = kd >> 5, kin = kd & 31, nb = n >> 7, nin = n & 127;
    uint32_t off = nin * 128 + kin * 4;
    off ^= (off >> 3) & 0x70;
    ((uint32_t*)dst)[((size_t)nb * (Kp / 32) + kc) * 4096 + (off >> 2)] = t;
}

// ------------------------- fused gather + interactions ----------------------
__global__ void interact_kernel(const void* __restrict__ cat,
                                const float* __restrict__ emb) {
    __shared__ float Zs[N_ROWS * EDIM];
    const int b = blockIdx.x;
    const int t = threadIdx.x;            // 384 threads
    const int lane = t & 31;
    const int warp = t >> 5;
    const int is64 = g_is64;

    for (int row = warp; row < N_ROWS; row += 12) {
        const float4* src;
        if (row < N_CAT) {
            long long idx;
            size_t e = (size_t)b * N_CAT + row;
            if (is64) idx = ((const long long*)cat)[e];
            else      idx = (long long)((const int*)cat)[e];
            src = (const float4*)(emb + ((long long)row * VOCAB + idx) * EDIM);
        } else {
            src = (const float4*)(g_dense + (size_t)b * EDIM);
        }
        ((float4*)(Zs + row * EDIM))[lane] = src[lane];
    }
    __syncthreads();

    if (t < N_PAIRS) {
        int i = 0, rem = t, rl = N_CAT;
        while (rem >= rl) { rem -= rl; rl--; i++; }
        int j = i + 1 + rem;
        const float4* zi = (const float4*)(Zs + i * EDIM);
        const float4* zj = (const float4*)(Zs + j * EDIM);
        float acc = 0.f;
        #pragma unroll
        for (int e = 0; e < EDIM / 4; e++) {
            float4 a = zi[e], c = zj[e];
            acc += a.x * c.x + a.y * c.y + a.z * c.z + a.w * c.w;
        }
        g_x0[(size_t)b * X0_LD + 128 + t] = acc;
    } else if (t == N_PAIRS) {
        g_x0[(size_t)b * X0_LD + (X0_LD - 1)] = 0.f;  // pad column
    }
}

// ------------------------- TF32 mma.sync GEMM -------------------------------
// C[M,N] = relu?(A[M,Kp] @ W + bias). CTA tile 128x128, 256 thr (8 warps,
// 2(M) x 4(N)), warp tile 64x32, mma m16n8k8 tf32, K-chunk 32, double-buffered
// smem, gmem prefetch in registers. A cvt->tf32 on fill; B pre-tiled/swizzled.
// smem: A0[0,16K) A1[16K,32K) B0[32K,48K) B1[48K,64K), SW128 swizzle.
__global__ __launch_bounds__(256) void tf32_gemm(
    const float* __restrict__ A, int lda,
    const float* __restrict__ Bt,
    const float* __restrict__ bias,
    float* __restrict__ C, int ldc,
    float* __restrict__ C2, int ldc2,
    int nc, int relu)
{
    extern __shared__ char smem[];
    const uint32_t sbase = smem_u32(smem);
    const int tid = threadIdx.x, l = tid & 31, w = tid >> 5;
    const int wm = w & 1, wn = w >> 1;
    const int rm = blockIdx.y * 128, bn = blockIdx.x * 128;

    // per-lane ldmatrix row bases (swizzle XOR masks constant per lane)
    uint32_t aoff[4], axor[4], boff[2], bxor[2];
    #pragma unroll
    for (int i = 0; i < 4; i++) {
        int m = wm * 64 + i * 16 + (l & 15);
        aoff[i] = m * 128; axor[i] = (m & 7) << 4;
    }
    #pragma unroll
    for (int j = 0; j < 2; j++) {
        int n = wn * 32 + j * 16 + (l & 7) + ((l & 16) >> 1);
        boff[j] = n * 128; bxor[j] = (n & 7) << 4;
    }
    const uint32_t alk = (uint32_t)((l >> 4) << 4);  // 0 | 16 (k lo/hi halves)
    const uint32_t blk = (uint32_t)((l & 8) << 1);   // 0 | 16

    float acc[4][4][4];
    #pragma unroll
    for (int i = 0; i < 4; i++)
        #pragma unroll
        for (int j = 0; j < 4; j++)
            #pragma unroll
            for (int q = 0; q < 4; q++) acc[i][j][q] = 0.f;

    // gmem streaming pointers
    const uint32_t arow = (uint32_t)(tid >> 1), ahalf = (uint32_t)(tid & 1);
    const float* aG = A + (size_t)(rm + arow) * lda + ahalf * 16;
    const float4* bG = (const float4*)Bt + (size_t)blockIdx.x * nc * 1024 + tid;

    float4 pa[4], pb[4];
    #pragma unroll
    for (int c = 0; c < 4; c++) pa[c] = *(const float4*)(aG + c * 4);
    #pragma unroll
    for (int c = 0; c < 4; c++) pb[c] = bG[c * 256];

    auto store_chunk = [&](int buf) {
        char* ab = smem + buf * 16384;
        char* bb = smem + 32768 + buf * 16384;
        #pragma unroll
        for (int c = 0; c < 4; c++) {
            uint4 wv;
            wv.x = f2tf32(pa[c].x); wv.y = f2tf32(pa[c].y);
            wv.z = f2tf32(pa[c].z); wv.w = f2tf32(pa[c].w);
            uint32_t off = arow * 128 + ahalf * 64 + c * 16;
            off ^= (off >> 3) & 0x70;
            *(uint4*)(ab + off) = wv;
        }
        #pragma unroll
        for (int c = 0; c < 4; c++) ((float4*)bb)[tid + 256 * c] = pb[c];
    };
    store_chunk(0);
    __syncthreads();

    for (int it = 0; it < nc; ++it) {
        const int cur = it & 1;
        if (it + 1 < nc) {   // prefetch next chunk into registers
            const float* ag = aG + (it + 1) * 32;
            #pragma unroll
            for (int c = 0; c < 4; c++) pa[c] = *(const float4*)(ag + c * 4);
            const float4* bg = bG + (size_t)(it + 1) * 1024;
            #pragma unroll
            for (int c = 0; c < 4; c++) pb[c] = bg[c * 256];
        }
        const uint32_t sA = sbase + cur * 16384;
        const uint32_t sB = sbase + 32768 + cur * 16384;

        #pragma unroll
        for (int ks = 0; ks < 4; ks++) {
            uint32_t af[4][4], bf[4][2];
            const uint32_t kA = ks * 32 + alk, kB = ks * 32 + blk;
            #pragma unroll
            for (int i = 0; i < 4; i++)
                ldsm4(sA + aoff[i] + (kA ^ axor[i]), af[i]);
            #pragma unroll
            for (int j = 0; j < 2; j++) {
                uint32_t r[4];
                ldsm4(sB + boff[j] + (kB ^ bxor[j]), r);
                bf[2 * j][0] = r[0]; bf[2 * j][1] = r[1];
                bf[2 * j + 1][0] = r[2]; bf[2 * j + 1][1] = r[3];
            }
            #pragma unroll
            for (int i = 0; i < 4; i++)
                #pragma unroll
                for (int j = 0; j < 4; j++)
                    asm volatile(
                        "mma.sync.aligned.m16n8k8.row.col.f32.tf32.tf32.f32 "
                        "{%0,%1,%2,%3}, {%4,%5,%6,%7}, {%8,%9}, {%0,%1,%2,%3};"
                        : "+f"(acc[i][j][0]), "+f"(acc[i][j][1]),
                          "+f"(acc[i][j][2]), "+f"(acc[i][j][3])
                        : "r"(af[i][0]), "r"(af[i][1]), "r"(af[i][2]), "r"(af[i][3]),
                          "r"(bf[j][0]), "r"(bf[j][1]));
        }

        if (it + 1 < nc) { store_chunk(cur ^ 1); __syncthreads(); }
    }

    // epilogue: lane l -> g = l>>2 (row in 8-group), t = l&3 (col pair)
    const int g = l >> 2, tt = l & 3;
    #pragma unroll
    for (int j = 0; j < 4; j++) {
        const int c0 = bn + wn * 32 + j * 8 + tt * 2;
        const float b0 = bias[c0], b1 = bias[c0 + 1];
        #pragma unroll
        for (int i = 0; i < 4; i++) {
            const int r0 = rm + wm * 64 + i * 16 + g;
            float v0 = acc[i][j][0] + b0, v1 = acc[i][j][1] + b1;
            float v2 = acc[i][j][2] + b0, v3 = acc[i][j][3] + b1;
            if (relu) {
                v0 = fmaxf(v0, 0.f); v1 = fmaxf(v1, 0.f);
                v2 = fmaxf(v2, 0.f); v3 = fmaxf(v3, 0.f);
            }
            *(float2*)(C + (size_t)r0 * ldc + c0)       = make_float2(v0, v1);
            *(float2*)(C + (size_t)(r0 + 8) * ldc + c0) = make_float2(v2, v3);
            if (C2) {
                *(float2*)(C2 + (size_t)r0 * ldc2 + c0)       = make_float2(v0, v1);
                *(float2*)(C2 + (size_t)(r0 + 8) * ldc2 + c0) = make_float2(v2, v3);
            }
        }
    }
}

// ------------------------- final dot + sigmoid -------------------------------
__global__ void final_kernel(const float* __restrict__ Wo,
                             const float* __restrict__ bo,
                             float* __restrict__ out) {
    __shared__ float ws[256];
    const int t = threadIdx.x;
    ws[t] = Wo[t];
    __syncthreads();
    const int lane = t & 31;
    const int warp = t >> 5;
    const int row = blockIdx.x * 8 + warp;
    const float* a = g_h2 + (size_t)row * 256;   // t4 lives in g_h2
    float acc = 0.f;
    #pragma unroll
    for (int q = 0; q < 8; q++)
        acc += a[lane + 32 * q] * ws[lane + 32 * q];
    #pragma unroll
    for (int off = 16; off; off >>= 1)
        acc += __shfl_down_sync(0xffffffffu, acc, off);
    if (lane == 0) {
        float x = acc + bo[0];
        out[row] = 1.f / (1.f + expf(-x));
    }
}

// ------------------------- launch ------------------------------------------
extern "C" void kernel_launch(void* const* d_in, const int* in_sizes, int n_in,
                              void* d_out, int out_size) {
    const float* dense_x = (const float*)d_in[0];
    const void*  cat_idx = d_in[1];
    const float* emb     = (const float*)d_in[2];
    const float* Wd1 = (const float*)d_in[3];
    const float* bd1 = (const float*)d_in[4];
    const float* Wd2 = (const float*)d_in[5];
    const float* bd2 = (const float*)d_in[6];
    const float* Wdf = (const float*)d_in[7];
    const float* bdf = (const float*)d_in[8];
    const float* Wt1 = (const float*)d_in[9];
    const float* bt1 = (const float*)d_in[10];
    const float* Wt2 = (const float*)d_in[11];
    const float* bt2 = (const float*)d_in[12];
    const float* Wt3 = (const float*)d_in[13];
    const float* bt3 = (const float*)d_in[14];
    const float* Wt4 = (const float*)d_in[15];
    const float* bt4 = (const float*)d_in[16];
    const float* Wo  = (const float*)d_in[17];
    const float* bo  = (const float*)d_in[18];
    float* out = (float*)d_out;

    float *p_h1, *p_h2, *p_dense, *p_x0, *p_t1, *p_t2;
    float *p_wd2t, *p_wdft, *p_wt1t, *p_wt2t, *p_wt3t, *p_wt4t;
    cudaGetSymbolAddress((void**)&p_h1, g_h1);
    cudaGetSymbolAddress((void**)&p_h2, g_h2);
    cudaGetSymbolAddress((void**)&p_dense, g_dense);
    cudaGetSymbolAddress((void**)&p_x0, g_x0);
    cudaGetSymbolAddress((void**)&p_t1, g_t1);
    cudaGetSymbolAddress((void**)&p_t2, g_t2);
    cudaGetSymbolAddress((void**)&p_wd2t, g_wd2t);
    cudaGetSymbolAddress((void**)&p_wdft, g_wdft);
    cudaGetSymbolAddress((void**)&p_wt1t, g_wt1t);
    cudaGetSymbolAddress((void**)&p_wt2t, g_wt2t);
    cudaGetSymbolAddress((void**)&p_wt3t, g_wt3t);
    cudaGetSymbolAddress((void**)&p_wt4t, g_wt4t);

    const int SMEM = 65536;   // A0 A1 B0 B1, 16KB each
    cudaFuncSetAttribute(tf32_gemm, cudaFuncAttributeMaxDynamicSharedMemorySize, SMEM);

    // 0. detect cat_idx dtype
    detect_idx_kernel<<<1, 256>>>((const unsigned int*)cat_idx);

    // 1. weight prep (tile + swizzle + tf32 convert), once per launch
    prep_w_kernel<<<(512  * 256  + 255) / 256, 256>>>(Wd2, p_wd2t, 512,  512,  256,  0);
    prep_w_kernel<<<(256  * 128  + 255) / 256, 256>>>(Wdf, p_wdft, 256,  256,  128,  0);
    prep_w_kernel<<<(480  * 1024 + 255) / 256, 256>>>(Wt1, p_wt1t, 479,  480,  1024, 1);
    prep_w_kernel<<<(1024 * 1024 + 255) / 256, 256>>>(Wt2, p_wt2t, 1024, 1024, 1024, 0);
    prep_w_kernel<<<(1024 * 512  + 255) / 256, 256>>>(Wt3, p_wt3t, 1024, 1024, 512,  0);
    prep_w_kernel<<<(512  * 256  + 255) / 256, 256>>>(Wt4, p_wt4t, 512,  512,  256,  0);

    // 2. bottom MLP layer 1: dense_x -> h1 (B x 512)
    dense1_kernel<<<BATCH / 4, 128>>>(dense_x, Wd1, bd1);

    // 3. h1 @ Wd2 -> h2 (B x 256)
    tf32_gemm<<<dim3(2, BATCH / 128), 256, SMEM>>>(
        p_h1, 512, p_wd2t, bd2, p_h2, 256, (float*)0, 0, 16, 1);

    // 4. h2 @ Wdf -> dense (B x 128) AND x0[:, 0:128]
    tf32_gemm<<<dim3(1, BATCH / 128), 256, SMEM>>>(
        p_h2, 256, p_wdft, bdf, p_dense, 128, p_x0, X0_LD, 8, 1);

    // 5. fused embedding gather + interactions -> x0[:, 128:479], pad 479
    interact_kernel<<<BATCH, 384>>>(cat_idx, emb);

    // 6. top MLP (Wt1 rows pre-permuted to match x0 layout)
    tf32_gemm<<<dim3(8, BATCH / 128), 256, SMEM>>>(
        p_x0, X0_LD, p_wt1t, bt1, p_t1, 1024, (float*)0, 0, 15, 1);
    tf32_gemm<<<dim3(8, BATCH / 128), 256, SMEM>>>(
        p_t1, 1024, p_wt2t, bt2, p_t2, 1024, (float*)0, 0, 32, 1);
    tf32_gemm<<<dim3(4, BATCH / 128), 256, SMEM>>>(
        p_t2, 1024, p_wt3t, bt3, p_h1, 512, (float*)0, 0, 32, 1);
    tf32_gemm<<<dim3(2, BATCH / 128), 256, SMEM>>>(
        p_h1, 512, p_wt4t, bt4, p_h2, 256, (float*)0, 0, 16, 1);

    // 7. t4 @ Wo + bo -> sigmoid -> out
    final_kernel<<<BATCH / 8, 256>>>(Wo, bo, out);
}

// round 16
// speedup vs baseline: 2.9733x; 1.3343x over previous
#include <cuda_runtime.h>
#include <cuda_fp16.h>
#include <math.h>
#include <stdint.h>

#define BATCH   16384
#define N_CAT   26
#define N_CONT  13
#define EDIM    128
#define VOCAB   100000
#define N_ROWS  27
#define N_PAIRS 351
#define X0_LD   512          // [0:128) dense | [128:479) interactions | [479:512) zero

// ------------------------- scratch (device globals) -------------------------
__device__ __half g_h1[BATCH * 512];    // bottom L1 out; reused as t3
__device__ __half g_h2[BATCH * 256];    // bottom L2 out; reused as t4
__device__ __half g_x0[BATCH * X0_LD];  // top MLP input
__device__ __half g_t1[BATCH * 1024];
__device__ __half g_t2[BATCH * 1024];
__device__ int    g_is64;

// tiled/swizzled fp16 weights: tiles of [128 N-rows x 64 K-halves] = 8192 halves (16KB)
__device__ __half g_wd2t[2 * 8  * 8192];   // 512x256
__device__ __half g_wdft[1 * 4  * 8192];   // 256x128
__device__ __half g_wt1t[8 * 8  * 8192];   // 512x1024 (remapped/padded)
__device__ __half g_wt2t[8 * 16 * 8192];   // 1024x1024
__device__ __half g_wt3t[4 * 16 * 8192];   // 1024x512
__device__ __half g_wt4t[2 * 8  * 8192];   // 512x256

// ------------------------- PTX helpers --------------------------------------
__device__ __forceinline__ uint32_t smem_u32(const void* p) {
    uint32_t a;
    asm("{ .reg .u64 t; cvta.to.shared.u64 t, %1; cvt.u32.u64 %0, t; }" : "=r"(a) : "l"(p));
    return a;
}
__device__ __forceinline__ void ldsm4(uint32_t addr, uint32_t* r) {
    asm volatile("ldmatrix.sync.aligned.m8n8.x4.shared.b16 {%0,%1,%2,%3}, [%4];"
                 : "=r"(r[0]), "=r"(r[1]), "=r"(r[2]), "=r"(r[3]) : "r"(addr));
}
__device__ __forceinline__ void cp16(uint32_t dst, const void* src) {
    asm volatile("cp.async.cg.shared.global [%0], [%1], 16;" :: "r"(dst), "l"(src));
}

// ------------------------- idx dtype detector -------------------------------
__global__ void detect_idx_kernel(const unsigned int* __restrict__ w) {
    __shared__ int ok;
    if (threadIdx.x == 0) ok = 1;
    __syncthreads();
    bool bad = false;
    for (int i = threadIdx.x; i < 2048; i += 256)
        if (w[2 * i + 1] != 0u) bad = true;
    if (bad) ok = 0;
    __syncthreads();
    if (threadIdx.x == 0) g_is64 = ok;
}

// ------------------------- bottom MLP layer 1 (K=13) ------------------------
__global__ void dense1_kernel(const float* __restrict__ X,
                              const float* __restrict__ W,
                              const float* __restrict__ bias) {
    __shared__ float xs[4][N_CONT];
    const int row0 = blockIdx.x * 4;
    const int t = threadIdx.x;
    if (t < 4 * N_CONT) xs[t / N_CONT][t % N_CONT] = X[(size_t)(row0 + t / N_CONT) * N_CONT + (t % N_CONT)];
    __syncthreads();
    const int n0 = t * 4;
    float4 acc[4];
    #pragma unroll
    for (int r = 0; r < 4; r++) acc[r] = make_float4(0.f, 0.f, 0.f, 0.f);
    #pragma unroll
    for (int k = 0; k < N_CONT; k++) {
        float4 w = *(const float4*)&W[k * 512 + n0];
        #pragma unroll
        for (int r = 0; r < 4; r++) {
            float xk = xs[r][k];
            acc[r].x += xk * w.x; acc[r].y += xk * w.y;
            acc[r].z += xk * w.z; acc[r].w += xk * w.w;
        }
    }
    float4 bb = *(const float4*)&bias[n0];
    #pragma unroll
    for (int r = 0; r < 4; r++) {
        __half2 p0 = __floats2half2_rn(fmaxf(acc[r].x + bb.x, 0.f), fmaxf(acc[r].y + bb.y, 0.f));
        __half2 p1 = __floats2half2_rn(fmaxf(acc[r].z + bb.z, 0.f), fmaxf(acc[r].w + bb.w, 0.f));
        __half2* dst = (__half2*)&g_h1[(size_t)(row0 + r) * 512 + n0];
        dst[0] = p0; dst[1] = p1;
    }
}

// ------------------------- weight tiling / swizzle prep ---------------------
// dst tile (nb, kc): 128 N-rows x 64 K-halves, 128B rows, SW128-swizzled fp16.
// remap!=0: Wt1 row permutation (dense rows 351..478 -> 0..127,
//           interaction rows 0..350 -> 128..478, rows 479..511 = zero pad)
__global__ void prep_w_kernel(const float* __restrict__ W, __half* __restrict__ dst,
                              int K, int Kp, int N, int remap) {
    int i = blockIdx.x * 256 + threadIdx.x;
    if (i >= Kp * N) return;
    int kd = i / N, n = i % N;
    int ks;
    if (remap) ks = (kd < 128) ? (kd + 351) : (kd < 479 ? kd - 128 : -1);
    else       ks = (kd < K) ? kd : -1;
    float v = (ks >= 0) ? W[(size_t)ks * N + n] : 0.f;
    int kc = kd >> 6, kin = kd & 63, nb = n >> 7, nin = n & 127;
    uint32_t off = nin * 128 + kin * 2;
    off ^= (off >> 3) & 0x70;
    dst[((size_t)nb * (Kp >> 6) + kc) * 8192 + (off >> 1)] = __float2half_rn(v);
}

// ------------------------- fused gather + interactions ----------------------
// Reads dense row fp16 from x0[:,0:128]; writes interactions fp16 to x0[:,128:479],
// zeros to [479:512).
__global__ void interact_kernel(const void* __restrict__ cat,
                                const float* __restrict__ emb) {
    __shared__ float Zs[N_ROWS * EDIM];
    const int b = blockIdx.x;
    const int t = threadIdx.x;            // 384 threads
    const int lane = t & 31;
    const int warp = t >> 5;
    const int is64 = g_is64;

    for (int row = warp; row < N_ROWS; row += 12) {
        if (row < N_CAT) {
            long long idx;
            size_t e = (size_t)b * N_CAT + row;
            if (is64) idx = ((const long long*)cat)[e];
            else      idx = (long long)((const int*)cat)[e];
            const float4* src = (const float4*)(emb + ((long long)row * VOCAB + idx) * EDIM);
            ((float4*)(Zs + row * EDIM))[lane] = src[lane];
        } else {
            const __half2* hp = (const __half2*)(g_x0 + (size_t)b * X0_LD);
            float2 f0 = __half22float2(hp[lane * 2]);
            float2 f1 = __half22float2(hp[lane * 2 + 1]);
            float* zd = Zs + row * EDIM + lane * 4;
            zd[0] = f0.x; zd[1] = f0.y; zd[2] = f1.x; zd[3] = f1.y;
        }
    }
    __syncthreads();

    if (t < N_PAIRS) {
        int i = 0, rem = t, rl = N_CAT;
        while (rem >= rl) { rem -= rl; rl--; i++; }
        int j = i + 1 + rem;
        const float4* zi = (const float4*)(Zs + i * EDIM);
        const float4* zj = (const float4*)(Zs + j * EDIM);
        float acc = 0.f;
        #pragma unroll
        for (int e = 0; e < EDIM / 4; e++) {
            float4 a = zi[e], c = zj[e];
            acc += a.x * c.x + a.y * c.y + a.z * c.z + a.w * c.w;
        }
        g_x0[(size_t)b * X0_LD + 128 + t] = __float2half_rn(acc);
    } else {
        // t = 351..383 -> cols 479..511 zero pad
        g_x0[(size_t)b * X0_LD + 128 + t] = __float2half_rn(0.f);
    }
}

// ------------------------- FP16 mma.sync GEMM -------------------------------
// C[M,N] = relu?(A[M,Kp] @ W + bias), fp32 accum, fp16 in/out.
// CTA tile 128x128, 256 thr (8 warps, 2(M) x 4(N)), warp tile 64x32,
// mma m16n8k16, K-chunk 64 halves (128B rows), cp.async double buffer.
// smem: A0[0,16K) A1[16K,32K) B0[32K,48K) B1[48K,64K), SW128 swizzle.
__global__ __launch_bounds__(256, 2) void h16_gemm(
    const __half* __restrict__ A, int lda,
    const __half* __restrict__ Bt,
    const float* __restrict__ bias,
    __half* __restrict__ C, int ldc,
    int nc, int relu)
{
    extern __shared__ char smem[];
    const uint32_t sbase = smem_u32(smem);
    const int tid = threadIdx.x, l = tid & 31, w = tid >> 5;
    const int wm = w & 1, wn = w >> 1;
    const int rm = blockIdx.y * 128, bn = blockIdx.x * 128;

    // per-lane ldmatrix bases (swizzle XOR constant per lane)
    uint32_t aoff[4], axor[4], boff[2], bxor[2];
    #pragma unroll
    for (int i = 0; i < 4; i++) {
        int m = wm * 64 + i * 16 + (l & 15);
        aoff[i] = m * 128; axor[i] = (m & 7) << 4;
    }
    #pragma unroll
    for (int j = 0; j < 2; j++) {
        int n = wn * 32 + j * 16 + (l & 7) + ((l & 16) >> 1);
        boff[j] = n * 128; bxor[j] = (n & 7) << 4;
    }
    const uint32_t alk = (uint32_t)((l >> 4) << 4);  // 0 | 16
    const uint32_t blk = (uint32_t)((l & 8) << 1);   // 0 | 16

    float acc[4][4][4];
    #pragma unroll
    for (int i = 0; i < 4; i++)
        #pragma unroll
        for (int j = 0; j < 4; j++)
            #pragma unroll
            for (int q = 0; q < 4; q++) acc[i][j][q] = 0.f;

    // cp.async source pointers
    const uint32_t arow = (uint32_t)(tid >> 1), ahalf = (uint32_t)(tid & 1);
    const __half* aG = A + (size_t)(rm + arow) * lda + ahalf * 32;
    const __half* bG = Bt + (size_t)blockIdx.x * nc * 8192 + tid * 8;

    uint32_t adst[4];
    #pragma unroll
    for (int c = 0; c < 4; c++) {
        uint32_t off = arow * 128 + ahalf * 64 + c * 16;
        off ^= (off >> 3) & 0x70;
        adst[c] = off;
    }

    auto issue = [&](int it, int buf) {
        const uint32_t ab = sbase + buf * 16384;
        const uint32_t bb = sbase + 32768 + buf * 16384;
        const __half* ag = aG + it * 64;
        const __half* bg = bG + (size_t)it * 8192;
        #pragma unroll
        for (int c = 0; c < 4; c++) cp16(ab + adst[c], ag + c * 8);
        #pragma unroll
        for (int c = 0; c < 4; c++) cp16(bb + tid * 16 + c * 4096, bg + c * 2048);
        asm volatile("cp.async.commit_group;" ::: "memory");
    };

    issue(0, 0);

    for (int it = 0; it < nc; ++it) {
        const int cur = it & 1;
        asm volatile("cp.async.wait_group 0;" ::: "memory");
        __syncthreads();
        if (it + 1 < nc) issue(it + 1, cur ^ 1);

        const uint32_t sA = sbase + cur * 16384;
        const uint32_t sB = sbase + 32768 + cur * 16384;

        #pragma unroll
        for (int ks = 0; ks < 4; ks++) {
            uint32_t af[4][4], bf[4][2];
            const uint32_t kA = ks * 32 + alk, kB = ks * 32 + blk;
            #pragma unroll
            for (int i = 0; i < 4; i++)
                ldsm4(sA + aoff[i] + (kA ^ axor[i]), af[i]);
            #pragma unroll
            for (int j = 0; j < 2; j++) {
                uint32_t r[4];
                ldsm4(sB + boff[j] + (kB ^ bxor[j]), r);
                bf[2 * j][0] = r[0]; bf[2 * j][1] = r[1];
                bf[2 * j + 1][0] = r[2]; bf[2 * j + 1][1] = r[3];
            }
            #pragma unroll
            for (int i = 0; i < 4; i++)
                #pragma unroll
                for (int j = 0; j < 4; j++)
                    asm volatile(
                        "mma.sync.aligned.m16n8k16.row.col.f32.f16.f16.f32 "
                        "{%0,%1,%2,%3}, {%4,%5,%6,%7}, {%8,%9}, {%0,%1,%2,%3};"
                        : "+f"(acc[i][j][0]), "+f"(acc[i][j][1]),
                          "+f"(acc[i][j][2]), "+f"(acc[i][j][3])
                        : "r"(af[i][0]), "r"(af[i][1]), "r"(af[i][2]), "r"(af[i][3]),
                          "r"(bf[j][0]), "r"(bf[j][1]));
        }
    }

    // epilogue: lane l -> g = l>>2 (row in 8-group), tt = l&3 (col pair)
    const int g = l >> 2, tt = l & 3;
    #pragma unroll
    for (int j = 0; j < 4; j++) {
        const int c0 = bn + wn * 32 + j * 8 + tt * 2;
        const float b0 = bias[c0], b1 = bias[c0 + 1];
        #pragma unroll
        for (int i = 0; i < 4; i++) {
            const int r0 = rm + wm * 64 + i * 16 + g;
            float v0 = acc[i][j][0] + b0, v1 = acc[i][j][1] + b1;
            float v2 = acc[i][j][2] + b0, v3 = acc[i][j][3] + b1;
            if (relu) {
                v0 = fmaxf(v0, 0.f); v1 = fmaxf(v1, 0.f);
                v2 = fmaxf(v2, 0.f); v3 = fmaxf(v3, 0.f);
            }
            *(__half2*)(C + (size_t)r0 * ldc + c0)       = __floats2half2_rn(v0, v1);
            *(__half2*)(C + (size_t)(r0 + 8) * ldc + c0) = __floats2half2_rn(v2, v3);
        }
    }
}

// ------------------------- final dot + sigmoid -------------------------------
__global__ void final_kernel(const float* __restrict__ Wo,
                             const float* __restrict__ bo,
                             float* __restrict__ out) {
    __shared__ float ws[256];
    const int t = threadIdx.x;
    ws[t] = Wo[t];
    __syncthreads();
    const int lane = t & 31;
    const int warp = t >> 5;
    const int row = blockIdx.x * 8 + warp;
    const __half* a = g_h2 + (size_t)row * 256;   // t4 lives in g_h2
    float acc = 0.f;
    #pragma unroll
    for (int q = 0; q < 8; q++)
        acc += __half2float(a[lane + 32 * q]) * ws[lane + 32 * q];
    #pragma unroll
    for (int off = 16; off; off >>= 1)
        acc += __shfl_down_sync(0xffffffffu, acc, off);
    if (lane == 0) {
        float x = acc + bo[0];
        out[row] = 1.f / (1.f + expf(-x));
    }
}

// ------------------------- launch ------------------------------------------
extern "C" void kernel_launch(void* const* d_in, const int* in_sizes, int n_in,
                              void* d_out, int out_size) {
    const float* dense_x = (const float*)d_in[0];
    const void*  cat_idx = d_in[1];
    const float* emb     = (const float*)d_in[2];
    const float* Wd1 = (const float*)d_in[3];
    const float* bd1 = (const float*)d_in[4];
    const float* Wd2 = (const float*)d_in[5];
    const float* bd2 = (const float*)d_in[6];
    const float* Wdf = (const float*)d_in[7];
    const float* bdf = (const float*)d_in[8];
    const float* Wt1 = (const float*)d_in[9];
    const float* bt1 = (const float*)d_in[10];
    const float* Wt2 = (const float*)d_in[11];
    const float* bt2 = (const float*)d_in[12];
    const float* Wt3 = (const float*)d_in[13];
    const float* bt3 = (const float*)d_in[14];
    const float* Wt4 = (const float*)d_in[15];
    const float* bt4 = (const float*)d_in[16];
    const float* Wo  = (const float*)d_in[17];
    const float* bo  = (const float*)d_in[18];
    float* out = (float*)d_out;

    __half *p_h1, *p_h2, *p_x0, *p_t1, *p_t2;
    __half *p_wd2t, *p_wdft, *p_wt1t, *p_wt2t, *p_wt3t, *p_wt4t;
    cudaGetSymbolAddress((void**)&p_h1, g_h1);
    cudaGetSymbolAddress((void**)&p_h2, g_h2);
    cudaGetSymbolAddress((void**)&p_x0, g_x0);
    cudaGetSymbolAddress((void**)&p_t1, g_t1);
    cudaGetSymbolAddress((void**)&p_t2, g_t2);
    cudaGetSymbolAddress((void**)&p_wd2t, g_wd2t);
    cudaGetSymbolAddress((void**)&p_wdft, g_wdft);
    cudaGetSymbolAddress((void**)&p_wt1t, g_wt1t);
    cudaGetSymbolAddress((void**)&p_wt2t, g_wt2t);
    cudaGetSymbolAddress((void**)&p_wt3t, g_wt3t);
    cudaGetSymbolAddress((void**)&p_wt4t, g_wt4t);

    const int SMEM = 65536;   // A0 A1 B0 B1, 16KB each
    cudaFuncSetAttribute(h16_gemm, cudaFuncAttributeMaxDynamicSharedMemorySize, SMEM);

    // 0. detect cat_idx dtype
    detect_idx_kernel<<<1, 256>>>((const unsigned int*)cat_idx);

    // 1. weight prep (tile + swizzle + fp16 convert), once per launch
    prep_w_kernel<<<(512  * 256  + 255) / 256, 256>>>(Wd2, p_wd2t, 512,  512,  256,  0);
    prep_w_kernel<<<(256  * 128  + 255) / 256, 256>>>(Wdf, p_wdft, 256,  256,  128,  0);
    prep_w_kernel<<<(512  * 1024 + 255) / 256, 256>>>(Wt1, p_wt1t, 479,  512,  1024, 1);
    prep_w_kernel<<<(1024 * 1024 + 255) / 256, 256>>>(Wt2, p_wt2t, 1024, 1024, 1024, 0);
    prep_w_kernel<<<(1024 * 512  + 255) / 256, 256>>>(Wt3, p_wt3t, 1024, 1024, 512,  0);
    prep_w_kernel<<<(512  * 256  + 255) / 256, 256>>>(Wt4, p_wt4t, 512,  512,  256,  0);

    // 2. bottom MLP layer 1: dense_x -> h1 (B x 512, fp16)
    dense1_kernel<<<BATCH / 4, 128>>>(dense_x, Wd1, bd1);

    // 3. h1 @ Wd2 -> h2 (B x 256)
    h16_gemm<<<dim3(2, BATCH / 128), 256, SMEM>>>(
        p_h1, 512, p_wd2t, bd2, p_h2, 256, 8, 1);

    // 4. h2 @ Wdf -> x0[:, 0:128]  (dense lives in x0)
    h16_gemm<<<dim3(1, BATCH / 128), 256, SMEM>>>(
        p_h2, 256, p_wdft, bdf, p_x0, X0_LD, 4, 1);

    // 5. fused embedding gather + interactions -> x0[:, 128:479], zeros 479:512
    interact_kernel<<<BATCH, 384>>>(cat_idx, emb);

    // 6. top MLP (Wt1 rows pre-permuted to match x0 layout, K padded to 512)
    h16_gemm<<<dim3(8, BATCH / 128), 256, SMEM>>>(
        p_x0, X0_LD, p_wt1t, bt1, p_t1, 1024, 8, 1);
    h16_gemm<<<dim3(8, BATCH / 128), 256, SMEM>>>(
        p_t1, 1024, p_wt2t, bt2, p_t2, 1024, 16, 1);
    h16_gemm<<<dim3(4, BATCH / 128), 256, SMEM>>>(
        p_t2, 1024, p_wt3t, bt3, p_h1, 512, 16, 1);   // t3 in g_h1
    h16_gemm<<<dim3(2, BATCH / 128), 256, SMEM>>>(
        p_h1, 512, p_wt4t, bt4, p_h2, 256, 8, 1);     // t4 in g_h2

    // 7. t4 @ Wo + bo -> sigmoid -> out
    final_kernel<<<BATCH / 8, 256>>>(Wo, bo, out);
}

// round 17
// speedup vs baseline: 7.0784x; 2.3807x over previous
#include <cuda_runtime.h>
#include <cuda_fp16.h>
#include <math.h>
#include <stdint.h>

#define BATCH   16384
#define N_CAT   26
#define N_CONT  13
#define EDIM    128
#define VOCAB   100000
#define N_ROWS  27
#define N_PAIRS 351
#define X0_LD   512          // [0:128) dense | [128:479) interactions | [479:512) zero

// ------------------------- scratch (device globals) -------------------------
__device__ __half g_h1[BATCH * 512];    // bottom L1 out; reused as t3
__device__ __half g_h2[BATCH * 256];    // bottom L2 out; reused as t4
__device__ __half g_x0[BATCH * X0_LD];  // top MLP input
__device__ __half g_t1[BATCH * 1024];
__device__ __half g_t2[BATCH * 1024];
__device__ int    g_is64;

// tiled/swizzled fp16 weights: tiles of [128 N-rows x 64 K-halves] = 8192 halves (16KB)
__device__ __half g_wd2t[2 * 8  * 8192];   // 512x256
__device__ __half g_wdft[1 * 4  * 8192];   // 256x128
__device__ __half g_wt1t[8 * 8  * 8192];   // 512x1024 (remapped/padded)
__device__ __half g_wt2t[8 * 16 * 8192];   // 1024x1024
__device__ __half g_wt3t[4 * 16 * 8192];   // 1024x512
__device__ __half g_wt4t[2 * 8  * 8192];   // 512x256

// ------------------------- PTX helpers --------------------------------------
__device__ __forceinline__ uint32_t smem_u32(const void* p) {
    uint32_t a;
    asm("{ .reg .u64 t; cvta.to.shared.u64 t, %1; cvt.u32.u64 %0, t; }" : "=r"(a) : "l"(p));
    return a;
}
__device__ __forceinline__ void ldsm4(uint32_t addr, uint32_t* r) {
    asm volatile("ldmatrix.sync.aligned.m8n8.x4.shared.b16 {%0,%1,%2,%3}, [%4];"
                 : "=r"(r[0]), "=r"(r[1]), "=r"(r[2]), "=r"(r[3]) : "r"(addr));
}
__device__ __forceinline__ void cp16(uint32_t dst, const void* src) {
    asm volatile("cp.async.cg.shared.global [%0], [%1], 16;" :: "r"(dst), "l"(src));
}
__device__ __forceinline__ void mma16816(float* d, const uint32_t* a, const uint32_t* b) {
    asm volatile(
        "mma.sync.aligned.m16n8k16.row.col.f32.f16.f16.f32 "
        "{%0,%1,%2,%3}, {%4,%5,%6,%7}, {%8,%9}, {%0,%1,%2,%3};"
        : "+f"(d[0]), "+f"(d[1]), "+f"(d[2]), "+f"(d[3])
        : "r"(a[0]), "r"(a[1]), "r"(a[2]), "r"(a[3]), "r"(b[0]), "r"(b[1]));
}

// ------------------------- idx dtype detector -------------------------------
__global__ void detect_idx_kernel(const unsigned int* __restrict__ w) {
    __shared__ int ok;
    if (threadIdx.x == 0) ok = 1;
    __syncthreads();
    bool bad = false;
    for (int i = threadIdx.x; i < 2048; i += 256)
        if (w[2 * i + 1] != 0u) bad = true;
    if (bad) ok = 0;
    __syncthreads();
    if (threadIdx.x == 0) g_is64 = ok;
}

// ------------------------- bottom MLP layer 1 (K=13) ------------------------
__global__ void dense1_kernel(const float* __restrict__ X,
                              const float* __restrict__ W,
                              const float* __restrict__ bias) {
    __shared__ float xs[4][N_CONT];
    const int row0 = blockIdx.x * 4;
    const int t = threadIdx.x;
    if (t < 4 * N_CONT) xs[t / N_CONT][t % N_CONT] = X[(size_t)(row0 + t / N_CONT) * N_CONT + (t % N_CONT)];
    __syncthreads();
    const int n0 = t * 4;
    float4 acc[4];
    #pragma unroll
    for (int r = 0; r < 4; r++) acc[r] = make_float4(0.f, 0.f, 0.f, 0.f);
    #pragma unroll
    for (int k = 0; k < N_CONT; k++) {
        float4 w = *(const float4*)&W[k * 512 + n0];
        #pragma unroll
        for (int r = 0; r < 4; r++) {
            float xk = xs[r][k];
            acc[r].x += xk * w.x; acc[r].y += xk * w.y;
            acc[r].z += xk * w.z; acc[r].w += xk * w.w;
        }
    }
    float4 bb = *(const float4*)&bias[n0];
    #pragma unroll
    for (int r = 0; r < 4; r++) {
        __half2 p0 = __floats2half2_rn(fmaxf(acc[r].x + bb.x, 0.f), fmaxf(acc[r].y + bb.y, 0.f));
        __half2 p1 = __floats2half2_rn(fmaxf(acc[r].z + bb.z, 0.f), fmaxf(acc[r].w + bb.w, 0.f));
        __half2* dst = (__half2*)&g_h1[(size_t)(row0 + r) * 512 + n0];
        dst[0] = p0; dst[1] = p1;
    }
}

// ------------------------- merged weight tiling / swizzle prep --------------
// All 6 weights in one launch; jobs dispatched by blockIdx range.
// dst tile (nb, kc): 128 N-rows x 64 K-halves, 128B rows, SW128-swizzled fp16.
__device__ __forceinline__ void prep_one(const float* __restrict__ W, __half* __restrict__ dst,
                                         int K, int Kp, int N, int remap, int i) {
    if (i >= Kp * N) return;
    int kd = i / N, n = i % N;
    int ks;
    if (remap) ks = (kd < 128) ? (kd + 351) : (kd < 479 ? kd - 128 : -1);
    else       ks = (kd < K) ? kd : -1;
    float v = (ks >= 0) ? W[(size_t)ks * N + n] : 0.f;
    int kc = kd >> 6, kin = kd & 63, nb = n >> 7, nin = n & 127;
    uint32_t off = nin * 128 + kin * 2;
    off ^= (off >> 3) & 0x70;
    dst[((size_t)nb * (Kp >> 6) + kc) * 8192 + (off >> 1)] = __float2half_rn(v);
}

struct PrepArgs {
    const float *wd2, *wdf, *wt1, *wt2, *wt3, *wt4;
};
// block ranges: wd2 [0,512) wdf [512,640) wt1 [640,2688) wt2 [2688,6784)
//               wt3 [6784,8832) wt4 [8832,9344)
__global__ void prep_all_kernel(PrepArgs a) {
    int blk = blockIdx.x;
    if (blk < 512)       prep_one(a.wd2, g_wd2t, 512,  512,  256,  0, (blk)        * 256 + threadIdx.x);
    else if (blk < 640)  prep_one(a.wdf, g_wdft, 256,  256,  128,  0, (blk - 512)  * 256 + threadIdx.x);
    else if (blk < 2688) prep_one(a.wt1, g_wt1t, 479,  512,  1024, 1, (blk - 640)  * 256 + threadIdx.x);
    else if (blk < 6784) prep_one(a.wt2, g_wt2t, 1024, 1024, 1024, 0, (blk - 2688) * 256 + threadIdx.x);
    else if (blk < 8832) prep_one(a.wt3, g_wt3t, 1024, 1024, 512,  0, (blk - 6784) * 256 + threadIdx.x);
    else                 prep_one(a.wt4, g_wt4t, 512,  512,  256,  0, (blk - 8832) * 256 + threadIdx.x);
}

// ------------------------- tensor-core gather + interactions ----------------
// One warp per sample: gather 27 rows (fp32 emb -> fp16, dense from x0) into
// Z (32 x 128 fp16, row stride 272B: conflict-free ldmatrix, rows 27-31 zero),
// compute S = Z*Z^T (32x32) via m16n8k16 fp16 MMA (fp32 accum), stage S in
// smem fp16, then write triu (351 vals) + zero pad to x0[:,128:512).
#define IW 8                      // warps (samples) per block
#define ZSTRIDE 136               // halves per row (272B)
#define ZBYTES  (32 * 272)        // 8704 per sample
#define SOFF    (IW * ZBYTES)     // 69632
#define ISMEM   (SOFF + IW * 2048)  // 86016
__global__ __launch_bounds__(256) void interact_kernel(const void* __restrict__ cat,
                                                       const float* __restrict__ emb) {
    extern __shared__ char ism[];
    const int tid = threadIdx.x, l = tid & 31, w = tid >> 5;
    const int b = blockIdx.x * IW + w;
    __half* Z = (__half*)(ism + w * ZBYTES);
    __half* S = (__half*)(ism + SOFF + w * 2048);
    const int is64 = g_is64;

    // gather: lane handles 4 elements (16B fp32 -> 8B fp16) per row
    #pragma unroll 1
    for (int r = 0; r < N_CAT; r++) {
        size_t e = (size_t)b * N_CAT + r;
        long long idx = is64 ? ((const long long*)cat)[e]
                             : (long long)((const int*)cat)[e];
        float4 v = ((const float4*)(emb + ((long long)r * VOCAB + idx) * EDIM))[l];
        __half2* zd = (__half2*)&Z[r * ZSTRIDE + l * 4];
        zd[0] = __floats2half2_rn(v.x, v.y);
        zd[1] = __floats2half2_rn(v.z, v.w);
    }
    // row 26 = dense (already fp16 in x0[:,0:128))
    *(uint2*)&Z[26 * ZSTRIDE + l * 4] = *(const uint2*)&g_x0[(size_t)b * X0_LD + l * 4];
    // rows 27..31 zero pad
    #pragma unroll
    for (int r = 27; r < 32; r++)
        *(uint2*)&Z[r * ZSTRIDE + l * 4] = make_uint2(0u, 0u);
    __syncwarp();

    // S = Z @ Z^T : 2 m16-tiles x 4 n8-tiles x 8 k16-steps
    const uint32_t Zu = smem_u32(Z);
    uint32_t zA[2], zB[2];
    #pragma unroll
    for (int i = 0; i < 2; i++)
        zA[i] = Zu + (uint32_t)(i * 16 + (l & 15)) * 272 + ((l >> 4) << 4);
    #pragma unroll
    for (int j = 0; j < 2; j++)
        zB[j] = Zu + (uint32_t)(j * 16 + (l & 7) + ((l & 16) >> 1)) * 272 + ((l & 8) << 1);

    float acc[2][4][4];
    #pragma unroll
    for (int i = 0; i < 2; i++)
        #pragma unroll
        for (int j = 0; j < 4; j++)
            #pragma unroll
            for (int q = 0; q < 4; q++) acc[i][j][q] = 0.f;

    #pragma unroll
    for (int ks = 0; ks < 8; ks++) {
        uint32_t af[2][4], bf[4][2];
        #pragma unroll
        for (int i = 0; i < 2; i++) ldsm4(zA[i] + ks * 32, af[i]);
        #pragma unroll
        for (int j = 0; j < 2; j++) {
            uint32_t r[4];
            ldsm4(zB[j] + ks * 32, r);
            bf[2 * j][0] = r[0]; bf[2 * j][1] = r[1];
            bf[2 * j + 1][0] = r[2]; bf[2 * j + 1][1] = r[3];
        }
        #pragma unroll
        for (int i = 0; i < 2; i++)
            #pragma unroll
            for (int j = 0; j < 4; j++)
                mma16816(acc[i][j], af[i], bf[j]);
    }

    // stage S (fp16) in smem
    #pragma unroll
    for (int i = 0; i < 2; i++)
        #pragma unroll
        for (int j = 0; j < 4; j++) {
            const int r0 = i * 16 + (l >> 2), c0 = j * 8 + (l & 3) * 2;
            *(__half2*)&S[r0 * 32 + c0]       = __floats2half2_rn(acc[i][j][0], acc[i][j][1]);
            *(__half2*)&S[(r0 + 8) * 32 + c0] = __floats2half2_rn(acc[i][j][2], acc[i][j][3]);
        }
    __syncwarp();

    // triu write-out: t = q*32 + lane covers 0..383 (351 pairs + 33 zero pads)
    __half* xrow = g_x0 + (size_t)b * X0_LD + 128;
    #pragma unroll
    for (int q = 0; q < 12; q++) {
        int t = q * 32 + l;
        __half val = __float2half_rn(0.f);
        if (t < N_PAIRS) {
            // row boundaries: 2809 - 8*offset(r) = (53-2r)^2 (exact in fp32)
            int r = (int)floorf((53.0f - sqrtf((float)(2809 - 8 * t))) * 0.5f);
            int c = r + 1 + (t - (r * (53 - r)) / 2);
            val = S[r * 32 + c];
        }
        xrow[t] = val;
    }
}

// ------------------------- FP16 mma.sync GEMM (3-stage pipeline) -------------
// C[M,N] = relu?(A[M,Kp] @ W + bias), fp32 accum, fp16 in/out.
// CTA tile 128x128, 256 thr (8 warps, 2(M) x 4(N)), warp tile 64x32,
// mma m16n8k16, K-chunk 64 halves (128B rows), cp.async 3-stage.
// smem: A0 A1 A2 [0,48K) B0 B1 B2 [48K,96K), SW128 swizzle.
__global__ __launch_bounds__(256, 2) void h16_gemm(
    const __half* __restrict__ A, int lda,
    const __half* __restrict__ Bt,
    const float* __restrict__ bias,
    __half* __restrict__ C, int ldc,
    int nc, int relu)
{
    extern __shared__ char smem[];
    const uint32_t sbase = smem_u32(smem);
    const int tid = threadIdx.x, l = tid & 31, w = tid >> 5;
    const int wm = w & 1, wn = w >> 1;
    const int rm = blockIdx.y * 128, bn = blockIdx.x * 128;

    uint32_t aoff[4], axor[4], boff[2], bxor[2];
    #pragma unroll
    for (int i = 0; i < 4; i++) {
        int m = wm * 64 + i * 16 + (l & 15);
        aoff[i] = m * 128; axor[i] = (m & 7) << 4;
    }
    #pragma unroll
    for (int j = 0; j < 2; j++) {
        int n = wn * 32 + j * 16 + (l & 7) + ((l & 16) >> 1);
        boff[j] = n * 128; bxor[j] = (n & 7) << 4;
    }
    const uint32_t alk = (uint32_t)((l >> 4) << 4);  // 0 | 16
    const uint32_t blk = (uint32_t)((l & 8) << 1);   // 0 | 16

    float acc[4][4][4];
    #pragma unroll
    for (int i = 0; i < 4; i++)
        #pragma unroll
        for (int j = 0; j < 4; j++)
            #pragma unroll
            for (int q = 0; q < 4; q++) acc[i][j][q] = 0.f;

    const uint32_t arow = (uint32_t)(tid >> 1), ahalf = (uint32_t)(tid & 1);
    const __half* aG = A + (size_t)(rm + arow) * lda + ahalf * 32;
    const __half* bG = Bt + (size_t)blockIdx.x * nc * 8192 + tid * 8;

    uint32_t adst[4];
    #pragma unroll
    for (int c = 0; c < 4; c++) {
        uint32_t off = arow * 128 + ahalf * 64 + c * 16;
        off ^= (off >> 3) & 0x70;
        adst[c] = off;
    }

    auto issue = [&](int it, int buf) {
        const uint32_t ab = sbase + buf * 16384;
        const uint32_t bb = sbase + 49152 + buf * 16384;
        const __half* ag = aG + it * 64;
        const __half* bg = bG + (size_t)it * 8192;
        #pragma unroll
        for (int c = 0; c < 4; c++) cp16(ab + adst[c], ag + c * 8);
        #pragma unroll
        for (int c = 0; c < 4; c++) cp16(bb + tid * 16 + c * 4096, bg + c * 2048);
        asm volatile("cp.async.commit_group;" ::: "memory");
    };

    issue(0, 0);
    if (nc > 1) issue(1, 1);

    for (int it = 0; it < nc; ++it) {
        const int cur = it % 3;
        if (it + 1 < nc) asm volatile("cp.async.wait_group 1;" ::: "memory");
        else             asm volatile("cp.async.wait_group 0;" ::: "memory");
        __syncthreads();
        if (it + 2 < nc) issue(it + 2, (it + 2) % 3);

        const uint32_t sA = sbase + cur * 16384;
        const uint32_t sB = sbase + 49152 + cur * 16384;

        #pragma unroll
        for (int ks = 0; ks < 4; ks++) {
            uint32_t af[4][4], bf[4][2];
            const uint32_t kA = ks * 32 + alk, kB = ks * 32 + blk;
            #pragma unroll
            for (int i = 0; i < 4; i++)
                ldsm4(sA + aoff[i] + (kA ^ axor[i]), af[i]);
            #pragma unroll
            for (int j = 0; j < 2; j++) {
                uint32_t r[4];
                ldsm4(sB + boff[j] + (kB ^ bxor[j]), r);
                bf[2 * j][0] = r[0]; bf[2 * j][1] = r[1];
                bf[2 * j + 1][0] = r[2]; bf[2 * j + 1][1] = r[3];
            }
            #pragma unroll
            for (int i = 0; i < 4; i++)
                #pragma unroll
                for (int j = 0; j < 4; j++)
                    mma16816(acc[i][j], af[i], bf[j]);
        }
    }

    const int g = l >> 2, tt = l & 3;
    #pragma unroll
    for (int j = 0; j < 4; j++) {
        const int c0 = bn + wn * 32 + j * 8 + tt * 2;
        const float b0 = bias[c0], b1 = bias[c0 + 1];
        #pragma unroll
        for (int i = 0; i < 4; i++) {
            const int r0 = rm + wm * 64 + i * 16 + g;
            float v0 = acc[i][j][0] + b0, v1 = acc[i][j][1] + b1;
            float v2 = acc[i][j][2] + b0, v3 = acc[i][j][3] + b1;
            if (relu) {
                v0 = fmaxf(v0, 0.f); v1 = fmaxf(v1, 0.f);
                v2 = fmaxf(v2, 0.f); v3 = fmaxf(v3, 0.f);
            }
            *(__half2*)(C + (size_t)r0 * ldc + c0)       = __floats2half2_rn(v0, v1);
            *(__half2*)(C + (size_t)(r0 + 8) * ldc + c0) = __floats2half2_rn(v2, v3);
        }
    }
}

// ------------------------- final dot + sigmoid -------------------------------
__global__ void final_kernel(const float* __restrict__ Wo,
                             const float* __restrict__ bo,
                             float* __restrict__ out) {
    __shared__ float ws[256];
    const int t = threadIdx.x;
    ws[t] = Wo[t];
    __syncthreads();
    const int lane = t & 31;
    const int warp = t >> 5;
    const int row = blockIdx.x * 8 + warp;
    const __half* a = g_h2 + (size_t)row * 256;   // t4 lives in g_h2
    float acc = 0.f;
    #pragma unroll
    for (int q = 0; q < 8; q++)
        acc += __half2float(a[lane + 32 * q]) * ws[lane + 32 * q];
    #pragma unroll
    for (int off = 16; off; off >>= 1)
        acc += __shfl_down_sync(0xffffffffu, acc, off);
    if (lane == 0) {
        float x = acc + bo[0];
        out[row] = 1.f / (1.f + expf(-x));
    }
}

// ------------------------- launch ------------------------------------------
extern "C" void kernel_launch(void* const* d_in, const int* in_sizes, int n_in,
                              void* d_out, int out_size) {
    const float* dense_x = (const float*)d_in[0];
    const void*  cat_idx = d_in[1];
    const float* emb     = (const float*)d_in[2];
    const float* Wd1 = (const float*)d_in[3];
    const float* bd1 = (const float*)d_in[4];
    const float* Wd2 = (const float*)d_in[5];
    const float* bd2 = (const float*)d_in[6];
    const float* Wdf = (const float*)d_in[7];
    const float* bdf = (const float*)d_in[8];
    const float* Wt1 = (const float*)d_in[9];
    const float* bt1 = (const float*)d_in[10];
    const float* Wt2 = (const float*)d_in[11];
    const float* bt2 = (const float*)d_in[12];
    const float* Wt3 = (const float*)d_in[13];
    const float* bt3 = (const float*)d_in[14];
    const float* Wt4 = (const float*)d_in[15];
    const float* bt4 = (const float*)d_in[16];
    const float* Wo  = (const float*)d_in[17];
    const float* bo  = (const float*)d_in[18];
    float* out = (float*)d_out;

    __half *p_h1, *p_h2, *p_x0, *p_t1, *p_t2;
    __half *p_wd2t, *p_wdft, *p_wt1t, *p_wt2t, *p_wt3t, *p_wt4t;
    cudaGetSymbolAddress((void**)&p_h1, g_h1);
    cudaGetSymbolAddress((void**)&p_h2, g_h2);
    cudaGetSymbolAddress((void**)&p_x0, g_x0);
    cudaGetSymbolAddress((void**)&p_t1, g_t1);
    cudaGetSymbolAddress((void**)&p_t2, g_t2);
    cudaGetSymbolAddress((void**)&p_wd2t, g_wd2t);
    cudaGetSymbolAddress((void**)&p_wdft, g_wdft);
    cudaGetSymbolAddress((void**)&p_wt1t, g_wt1t);
    cudaGetSymbolAddress((void**)&p_wt2t, g_wt2t);
    cudaGetSymbolAddress((void**)&p_wt3t, g_wt3t);
    cudaGetSymbolAddress((void**)&p_wt4t, g_wt4t);

    const int SMEM = 98304;   // 3-stage: A x3 + B x3, 16KB each
    cudaFuncSetAttribute(h16_gemm, cudaFuncAttributeMaxDynamicSharedMemorySize, SMEM);
    cudaFuncSetAttribute(interact_kernel, cudaFuncAttributeMaxDynamicSharedMemorySize, ISMEM);

    // 0. detect cat_idx dtype
    detect_idx_kernel<<<1, 256>>>((const unsigned int*)cat_idx);

    // 1. merged weight prep (tile + swizzle + fp16), once per launch
    PrepArgs pa{Wd2, Wdf, Wt1, Wt2, Wt3, Wt4};
    prep_all_kernel<<<9344, 256>>>(pa);

    // 2. bottom MLP layer 1: dense_x -> h1 (B x 512, fp16)
    dense1_kernel<<<BATCH / 4, 128>>>(dense_x, Wd1, bd1);

    // 3. h1 @ Wd2 -> h2 (B x 256)
    h16_gemm<<<dim3(2, BATCH / 128), 256, SMEM>>>(
        p_h1, 512, p_wd2t, bd2, p_h2, 256, 8, 1);

    // 4. h2 @ Wdf -> x0[:, 0:128]  (dense lives in x0)
    h16_gemm<<<dim3(1, BATCH / 128), 256, SMEM>>>(
        p_h2, 256, p_wdft, bdf, p_x0, X0_LD, 4, 1);

    // 5. tensor-core gather + interactions -> x0[:, 128:479], zeros 479:512
    interact_kernel<<<BATCH / IW, 256, ISMEM>>>(cat_idx, emb);

    // 6. top MLP (Wt1 rows pre-permuted to match x0 layout, K padded to 512)
    h16_gemm<<<dim3(8, BATCH / 128), 256, SMEM>>>(
        p_x0, X0_LD, p_wt1t, bt1, p_t1, 1024, 8, 1);
    h16_gemm<<<dim3(8, BATCH / 128), 256, SMEM>>>(
        p_t1, 1024, p_wt2t, bt2, p_t2, 1024, 16, 1);
    h16_gemm<<<dim3(4, BATCH / 128), 256, SMEM>>>(
        p_t2, 1024, p_wt3t, bt3, p_h1, 512, 16, 1);   // t3 in g_h1
    h16_gemm<<<dim3(2, BATCH / 128), 256, SMEM>>>(
        p_h1, 512, p_wt4t, bt4, p_h2, 256, 8, 1);     // t4 in g_h2

    // 7. t4 @ Wo + bo -> sigmoid -> out
    final_kernel<<<BATCH / 8, 256>>>(Wo, bo, out);
}